// round 5
// baseline (speedup 1.0000x reference)
#include <cuda_runtime.h>
#include <cuda_bf16.h>
#include <cstdint>

// Problem constants (fixed by the dataset)
#define BATCH 2
#define NSEQ  2048
#define CDIM  1024
#define HH    16
#define DD    64
#define RLORA 16
#define MROWS (BATCH * NSEQ)        // 4096
#define NQKV  (3 * CDIM)            // 3072
#define LORA_SCALE 2.0f

// ---------------------------------------------------------------------------
// Scratch (static device globals; no allocation allowed)
// ---------------------------------------------------------------------------
__device__ float g_qkv[MROWS * NQKV];   // 50.3 MB
__device__ float g_ao [MROWS * CDIM];   // 16.8 MB
__device__ float g_t  [MROWS * RLORA];
__device__ float g_t2 [MROWS * RLORA];

// ---------------------------------------------------------------------------
// t = (X @ A^T) * LORA_SCALE   -- X [M,1024], A [16,1024], t [M,16]
// one block per row, 128 threads
// ---------------------------------------------------------------------------
__global__ __launch_bounds__(128) void lora_t_kernel(
    const float* __restrict__ X, const float* __restrict__ A,
    float* __restrict__ T)
{
    int m   = blockIdx.x;
    int tid = threadIdx.x;
    const float* xr = X + (size_t)m * CDIM;

    float acc[RLORA];
#pragma unroll
    for (int j = 0; j < RLORA; j++) acc[j] = 0.f;

    for (int k = tid; k < CDIM; k += 128) {
        float xv = xr[k];
#pragma unroll
        for (int j = 0; j < RLORA; j++)
            acc[j] += xv * A[j * CDIM + k];
    }

    __shared__ float red[RLORA][4];
    int lane = tid & 31, w = tid >> 5;
#pragma unroll
    for (int j = 0; j < RLORA; j++) {
        float v = acc[j];
#pragma unroll
        for (int off = 16; off; off >>= 1)
            v += __shfl_xor_sync(0xffffffffu, v, off);
        if (lane == 0) red[j][w] = v;
    }
    __syncthreads();
    if (tid < RLORA) {
        float v = red[tid][0] + red[tid][1] + red[tid][2] + red[tid][3];
        T[m * RLORA + tid] = v * LORA_SCALE;
    }
}

// ---------------------------------------------------------------------------
// C[M,Nout] = A[M,K] @ W[Nout,K]^T + bias[n] + T[M,16] @ Bl[Nout,16]^T
// Tile: BM=128, BN=128, BK=16. 256 threads (16x16), each computes 8x8 as
// FOUR 4x4 quadrants at (ty*4 / 64+ty*4) x (tx*4 / 64+tx*4): all smem
// LDS.128 phases cover words 0..31 exactly once -> conflict-free.
// Double-buffered smem, register prefetch, 1 barrier per k-step.
// Rank-16 LoRA term runs as one extra mainloop-style k-block on transposed
// Ts/Bs tiles (conflict-free), then bias + store.
// Dynamic smem: 2 bufs x (As 16x132 + Ws 16x132) = 8448 floats = 33792 B.
// ---------------------------------------------------------------------------
#define GBM 128
#define GBN 128
#define GBK 16
#define APAD 132              // padded row stride (floats); %4==0 keeps f4 aligned
#define TILEF (GBK * APAD)    // 2112 floats per tile
#define GEMM_SMEM_BYTES (4 * TILEF * 4)   // 33792

__global__ __launch_bounds__(256) void gemm_lora_kernel(
    const float* __restrict__ A, const float* __restrict__ W,
    const float* __restrict__ bias, const float* __restrict__ T,
    const float* __restrict__ Bl, float* __restrict__ C,
    int K, int Nout)
{
    extern __shared__ float sm[];
    // layout: As0 | As1 | Ws0 | Ws1
    float* AsBuf[2] = { sm,             sm + TILEF };
    float* WsBuf[2] = { sm + 2 * TILEF, sm + 3 * TILEF };

    int tid = threadIdx.x;
    int tx = tid & 15, ty = tid >> 4;
    int m0 = blockIdx.y * GBM;
    int n0 = blockIdx.x * GBN;

    // loader indices: 512 float4 per matrix tile, 2 per thread
    int lrow0 = tid >> 2,          lkq0 = tid & 3;          // lin = tid
    int lrow1 = (tid + 256) >> 2,  lkq1 = (tid + 256) & 3;  // lin = tid+256

    float acc[8][8];
#pragma unroll
    for (int i = 0; i < 8; i++)
#pragma unroll
        for (int j = 0; j < 8; j++) acc[i][j] = 0.f;

    const int KT = K / GBK;

    // ---- preload tile 0 ----
    {
        float4 va0 = *(const float4*)&A[(size_t)(m0 + lrow0) * K + lkq0 * 4];
        float4 va1 = *(const float4*)&A[(size_t)(m0 + lrow1) * K + lkq1 * 4];
        float4 vw0 = *(const float4*)&W[(size_t)(n0 + lrow0) * K + lkq0 * 4];
        float4 vw1 = *(const float4*)&W[(size_t)(n0 + lrow1) * K + lkq1 * 4];
        float* As = AsBuf[0]; float* Ws = WsBuf[0];
        As[(lkq0 * 4 + 0) * APAD + lrow0] = va0.x; As[(lkq0 * 4 + 1) * APAD + lrow0] = va0.y;
        As[(lkq0 * 4 + 2) * APAD + lrow0] = va0.z; As[(lkq0 * 4 + 3) * APAD + lrow0] = va0.w;
        As[(lkq1 * 4 + 0) * APAD + lrow1] = va1.x; As[(lkq1 * 4 + 1) * APAD + lrow1] = va1.y;
        As[(lkq1 * 4 + 2) * APAD + lrow1] = va1.z; As[(lkq1 * 4 + 3) * APAD + lrow1] = va1.w;
        Ws[(lkq0 * 4 + 0) * APAD + lrow0] = vw0.x; Ws[(lkq0 * 4 + 1) * APAD + lrow0] = vw0.y;
        Ws[(lkq0 * 4 + 2) * APAD + lrow0] = vw0.z; Ws[(lkq0 * 4 + 3) * APAD + lrow0] = vw0.w;
        Ws[(lkq1 * 4 + 0) * APAD + lrow1] = vw1.x; Ws[(lkq1 * 4 + 1) * APAD + lrow1] = vw1.y;
        Ws[(lkq1 * 4 + 2) * APAD + lrow1] = vw1.z; Ws[(lkq1 * 4 + 3) * APAD + lrow1] = vw1.w;
    }
    __syncthreads();

    for (int kt = 0; kt < KT; kt++) {
        float4 pa0, pa1, pw0, pw1;
        bool has_next = (kt + 1 < KT);
        if (has_next) {
            int kb = (kt + 1) * GBK;
            pa0 = *(const float4*)&A[(size_t)(m0 + lrow0) * K + kb + lkq0 * 4];
            pa1 = *(const float4*)&A[(size_t)(m0 + lrow1) * K + kb + lkq1 * 4];
            pw0 = *(const float4*)&W[(size_t)(n0 + lrow0) * K + kb + lkq0 * 4];
            pw1 = *(const float4*)&W[(size_t)(n0 + lrow1) * K + kb + lkq1 * 4];
        }

        const float* As = AsBuf[kt & 1];
        const float* Ws = WsBuf[kt & 1];
#pragma unroll
        for (int kk = 0; kk < GBK; kk++) {
            float4 a0 = *(const float4*)&As[kk * APAD + ty * 4];
            float4 a1 = *(const float4*)&As[kk * APAD + 64 + ty * 4];
            float4 b0 = *(const float4*)&Ws[kk * APAD + tx * 4];
            float4 b1 = *(const float4*)&Ws[kk * APAD + 64 + tx * 4];
            float av[8] = {a0.x, a0.y, a0.z, a0.w, a1.x, a1.y, a1.z, a1.w};
            float bv[8] = {b0.x, b0.y, b0.z, b0.w, b1.x, b1.y, b1.z, b1.w};
#pragma unroll
            for (int i = 0; i < 8; i++)
#pragma unroll
                for (int j = 0; j < 8; j++)
                    acc[i][j] += av[i] * bv[j];
        }

        if (has_next) {
            float* Asn = AsBuf[(kt + 1) & 1];
            float* Wsn = WsBuf[(kt + 1) & 1];
            Asn[(lkq0 * 4 + 0) * APAD + lrow0] = pa0.x; Asn[(lkq0 * 4 + 1) * APAD + lrow0] = pa0.y;
            Asn[(lkq0 * 4 + 2) * APAD + lrow0] = pa0.z; Asn[(lkq0 * 4 + 3) * APAD + lrow0] = pa0.w;
            Asn[(lkq1 * 4 + 0) * APAD + lrow1] = pa1.x; Asn[(lkq1 * 4 + 1) * APAD + lrow1] = pa1.y;
            Asn[(lkq1 * 4 + 2) * APAD + lrow1] = pa1.z; Asn[(lkq1 * 4 + 3) * APAD + lrow1] = pa1.w;
            Wsn[(lkq0 * 4 + 0) * APAD + lrow0] = pw0.x; Wsn[(lkq0 * 4 + 1) * APAD + lrow0] = pw0.y;
            Wsn[(lkq0 * 4 + 2) * APAD + lrow0] = pw0.z; Wsn[(lkq0 * 4 + 3) * APAD + lrow0] = pw0.w;
            Wsn[(lkq1 * 4 + 0) * APAD + lrow1] = pw1.x; Wsn[(lkq1 * 4 + 1) * APAD + lrow1] = pw1.y;
            Wsn[(lkq1 * 4 + 2) * APAD + lrow1] = pw1.z; Wsn[(lkq1 * 4 + 3) * APAD + lrow1] = pw1.w;
            __syncthreads();
        }
    }

    // ---- rank-16 LoRA update as one extra k-block on transposed tiles ----
    __syncthreads();                      // mainloop reads fully drained
    float* TsT = sm;                      // [16][132]  [l][m-row]
    float* BsT = sm + TILEF;              // [16][132]  [l][n-row]
    {
        // load T/Bl rows (float4) and store transposed, same pattern as tiles
        float4 t0 = *(const float4*)&T [(size_t)(m0 + lrow0) * RLORA + lkq0 * 4];
        float4 t1 = *(const float4*)&T [(size_t)(m0 + lrow1) * RLORA + lkq1 * 4];
        float4 u0 = *(const float4*)&Bl[(size_t)(n0 + lrow0) * RLORA + lkq0 * 4];
        float4 u1 = *(const float4*)&Bl[(size_t)(n0 + lrow1) * RLORA + lkq1 * 4];
        TsT[(lkq0 * 4 + 0) * APAD + lrow0] = t0.x; TsT[(lkq0 * 4 + 1) * APAD + lrow0] = t0.y;
        TsT[(lkq0 * 4 + 2) * APAD + lrow0] = t0.z; TsT[(lkq0 * 4 + 3) * APAD + lrow0] = t0.w;
        TsT[(lkq1 * 4 + 0) * APAD + lrow1] = t1.x; TsT[(lkq1 * 4 + 1) * APAD + lrow1] = t1.y;
        TsT[(lkq1 * 4 + 2) * APAD + lrow1] = t1.z; TsT[(lkq1 * 4 + 3) * APAD + lrow1] = t1.w;
        BsT[(lkq0 * 4 + 0) * APAD + lrow0] = u0.x; BsT[(lkq0 * 4 + 1) * APAD + lrow0] = u0.y;
        BsT[(lkq0 * 4 + 2) * APAD + lrow0] = u0.z; BsT[(lkq0 * 4 + 3) * APAD + lrow0] = u0.w;
        BsT[(lkq1 * 4 + 0) * APAD + lrow1] = u1.x; BsT[(lkq1 * 4 + 1) * APAD + lrow1] = u1.y;
        BsT[(lkq1 * 4 + 2) * APAD + lrow1] = u1.z; BsT[(lkq1 * 4 + 3) * APAD + lrow1] = u1.w;
    }
    __syncthreads();

#pragma unroll
    for (int l = 0; l < RLORA; l++) {
        float4 a0 = *(const float4*)&TsT[l * APAD + ty * 4];
        float4 a1 = *(const float4*)&TsT[l * APAD + 64 + ty * 4];
        float4 b0 = *(const float4*)&BsT[l * APAD + tx * 4];
        float4 b1 = *(const float4*)&BsT[l * APAD + 64 + tx * 4];
        float av[8] = {a0.x, a0.y, a0.z, a0.w, a1.x, a1.y, a1.z, a1.w};
        float bv[8] = {b0.x, b0.y, b0.z, b0.w, b1.x, b1.y, b1.z, b1.w};
#pragma unroll
        for (int i = 0; i < 8; i++)
#pragma unroll
            for (int j = 0; j < 8; j++)
                acc[i][j] += av[i] * bv[j];
    }

    // ---- bias + store: rows {ty*4+i, 64+ty*4+i}, cols {tx*4+j, 64+tx*4+j} --
    float bv0[8];
#pragma unroll
    for (int j = 0; j < 4; j++) {
        bv0[j]     = bias[n0 + tx * 4 + j];
        bv0[4 + j] = bias[n0 + 64 + tx * 4 + j];
    }

#pragma unroll
    for (int i = 0; i < 8; i++) {
        int m = m0 + (i < 4 ? ty * 4 + i : 64 + ty * 4 + (i - 4));
        float lo[4], hi[4];
#pragma unroll
        for (int j = 0; j < 4; j++) {
            lo[j] = acc[i][j]     + bv0[j];
            hi[j] = acc[i][4 + j] + bv0[4 + j];
        }
        *(float4*)&C[(size_t)m * Nout + n0 + tx * 4]      = *(float4*)&lo[0];
        *(float4*)&C[(size_t)m * Nout + n0 + 64 + tx * 4] = *(float4*)&hi[0];
    }
}

// ---------------------------------------------------------------------------
// Flash attention, fp32. One block = 128 queries for one (b,h).
// Key tiles of 64. Online softmax with key-padding mask.
// Each thread owns 8 q-rows (quadrants ty*4+i and 64+ty*4+i) x 4 d/k-cols.
// qsT/ksT stored [d][row] so QK inner loop is 3x LDS.128 + 32 FFMA.
// ps stored [q][kc] stride 68; PV is 12x LDS.128 + 128 FFMA per 4-kc chunk.
// Dynamic smem: qsT 32KB + ksT 16KB + vs 16KB + ps 34.8KB + mask = 100864 B.
// 2 CTAs/SM by smem.
// ---------------------------------------------------------------------------
#define FBQ 128
#define PSST 68
#define FLASH_SMEM_BYTES ((64 * FBQ + 4096 + 4096 + FBQ * PSST) * 4 + 64 * 4)

__global__ __launch_bounds__(256) void flash_kernel(
    const float* __restrict__ qkv, const int* __restrict__ amask,
    float* __restrict__ ao)
{
    extern __shared__ float smf[];
    float* qsT = smf;                         // [64][128]  [d][qrow]
    float* ksT = smf + 64 * FBQ;              // [64][64]   [d][krow]
    float* vs  = smf + 64 * FBQ + 4096;       // [64][64]   [krow][d]
    float* ps  = smf + 64 * FBQ + 8192;       // [128][68]  [qrow][kc]
    int*   mk  = (int*)(smf + 64 * FBQ + 8192 + FBQ * PSST);

    int bh = blockIdx.y;
    int b  = bh >> 4, h = bh & 15;
    int q0 = blockIdx.x * FBQ;
    int tid = threadIdx.x, tx = tid & 15, ty = tid >> 4;
    const float scale = 0.125f;       // d^-0.5, d=64
    size_t rowbase = (size_t)b * NSEQ;

    // Load Q tile (128 rows x 16 float4 = 2048 f4, 8 per thread),
    // store transposed & pre-scaled.
#pragma unroll
    for (int i = 0; i < 8; i++) {
        int idx = tid + i * 256;      // 0..2047: row=idx/16, f4=idx%16
        int row = idx >> 4, f4 = idx & 15;
        float4 v = *(const float4*)&qkv[(rowbase + q0 + row) * NQKV + h * DD + f4 * 4];
        qsT[(f4 * 4 + 0) * FBQ + row] = v.x * scale;
        qsT[(f4 * 4 + 1) * FBQ + row] = v.y * scale;
        qsT[(f4 * 4 + 2) * FBQ + row] = v.z * scale;
        qsT[(f4 * 4 + 3) * FBQ + row] = v.w * scale;
    }

    float m_i[8], l_i[8], o[8][4];
#pragma unroll
    for (int i = 0; i < 8; i++) {
        m_i[i] = -1e30f; l_i[i] = 0.f;
#pragma unroll
        for (int j = 0; j < 4; j++) o[i][j] = 0.f;
    }

    for (int kt = 0; kt < NSEQ / 64; kt++) {
        int k0 = kt * 64;
        __syncthreads();   // prior PV reads (vs, ps) done before overwrite

        // Load K (transposed) and V (direct) tiles: 64 rows x 16 float4
#pragma unroll
        for (int i = 0; i < 4; i++) {
            int idx = tid + i * 256;
            int row = idx >> 4, f4 = idx & 15;
            size_t g = (rowbase + k0 + row) * NQKV + h * DD + f4 * 4;
            float4 kv = *(const float4*)&qkv[g + CDIM];
            ksT[(f4 * 4 + 0) * 64 + row] = kv.x;
            ksT[(f4 * 4 + 1) * 64 + row] = kv.y;
            ksT[(f4 * 4 + 2) * 64 + row] = kv.z;
            ksT[(f4 * 4 + 3) * 64 + row] = kv.w;
            float4 vv = *(const float4*)&qkv[g + 2 * CDIM];
            *(float4*)&vs[row * 64 + f4 * 4] = vv;
        }
        if (tid < 64) mk[tid] = amask[b * NSEQ + k0 + tid];
        __syncthreads();

        // S = Q K^T : 8 q-rows (two quadrants) x 4 k-cols per thread
        float s[8][4];
#pragma unroll
        for (int i = 0; i < 8; i++)
#pragma unroll
            for (int j = 0; j < 4; j++) s[i][j] = 0.f;

#pragma unroll 8
        for (int kk = 0; kk < DD; kk++) {
            float4 a0 = *(const float4*)&qsT[kk * FBQ + ty * 4];
            float4 a1 = *(const float4*)&qsT[kk * FBQ + 64 + ty * 4];
            float4 b4 = *(const float4*)&ksT[kk * 64 + tx * 4];
            float av[8] = {a0.x, a0.y, a0.z, a0.w, a1.x, a1.y, a1.z, a1.w};
            float bvv[4] = {b4.x, b4.y, b4.z, b4.w};
#pragma unroll
            for (int i = 0; i < 8; i++)
#pragma unroll
                for (int j = 0; j < 4; j++)
                    s[i][j] += av[i] * bvv[j];
        }

        float mjf[4];
#pragma unroll
        for (int j = 0; j < 4; j++) mjf[j] = mk[tx * 4 + j] ? 1.f : 0.f;

#pragma unroll
        for (int i = 0; i < 8; i++) {
            int qrow = (i < 4) ? (ty * 4 + i) : (64 + ty * 4 + (i - 4));
            float smv[4];
#pragma unroll
            for (int j = 0; j < 4; j++)
                smv[j] = mjf[j] > 0.f ? s[i][j] : -1e30f;
            float rmax = fmaxf(fmaxf(smv[0], smv[1]), fmaxf(smv[2], smv[3]));
#pragma unroll
            for (int off = 8; off; off >>= 1)
                rmax = fmaxf(rmax, __shfl_xor_sync(0xffffffffu, rmax, off, 16));
            float mnew = fmaxf(m_i[i], rmax);
            float corr = __expf(m_i[i] - mnew);
            m_i[i] = mnew;
            float p[4];
#pragma unroll
            for (int j = 0; j < 4; j++)
                p[j] = __expf(smv[j] - mnew) * mjf[j];   // masked -> exactly 0
            float rs = (p[0] + p[1]) + (p[2] + p[3]);
#pragma unroll
            for (int off = 8; off; off >>= 1)
                rs += __shfl_xor_sync(0xffffffffu, rs, off, 16);
            l_i[i] = l_i[i] * corr + rs;
#pragma unroll
            for (int j = 0; j < 4; j++) o[i][j] *= corr;
            *(float4*)&ps[qrow * PSST + tx * 4] = *(float4*)&p[0];
        }
        __syncthreads();

        // O += P V : 8 q-rows x 4 d-cols per thread, kc in chunks of 4
#pragma unroll 4
        for (int c4 = 0; c4 < 16; c4++) {
            int kc0 = c4 * 4;
            float4 pr[8], vr[4];
#pragma unroll
            for (int i = 0; i < 4; i++) {
                pr[i]     = *(const float4*)&ps[(ty * 4 + i) * PSST + kc0];
                pr[4 + i] = *(const float4*)&ps[(64 + ty * 4 + i) * PSST + kc0];
            }
#pragma unroll
            for (int r = 0; r < 4; r++)
                vr[r] = *(const float4*)&vs[(kc0 + r) * 64 + tx * 4];
#pragma unroll
            for (int i = 0; i < 8; i++) {
                float pv[4] = {pr[i].x, pr[i].y, pr[i].z, pr[i].w};
#pragma unroll
                for (int r = 0; r < 4; r++) {
                    o[i][0] += pv[r] * vr[r].x;
                    o[i][1] += pv[r] * vr[r].y;
                    o[i][2] += pv[r] * vr[r].z;
                    o[i][3] += pv[r] * vr[r].w;
                }
            }
        }
    }

    // Normalize and store to [B*N, C] with col = h*64 + d
#pragma unroll
    for (int i = 0; i < 8; i++) {
        int qrow = (i < 4) ? (ty * 4 + i) : (64 + ty * 4 + (i - 4));
        float inv = 1.0f / l_i[i];
        size_t row = rowbase + q0 + qrow;
        float outv[4];
#pragma unroll
        for (int j = 0; j < 4; j++) outv[j] = o[i][j] * inv;
        *(float4*)&ao[row * CDIM + h * DD + tx * 4] = *(float4*)&outv[0];
    }
}

// ---------------------------------------------------------------------------
// Launch
// ---------------------------------------------------------------------------
extern "C" void kernel_launch(void* const* d_in, const int* in_sizes, int n_in,
                              void* d_out, int out_size)
{
    const float* x    = (const float*)d_in[0];
    const int*   mask = (const int*)  d_in[1];
    const float* Wqkv = (const float*)d_in[2];
    const float* bqkv = (const float*)d_in[3];
    const float* Aqkv = (const float*)d_in[4];
    const float* Bqkv = (const float*)d_in[5];
    const float* Wp   = (const float*)d_in[6];
    const float* bp   = (const float*)d_in[7];
    const float* Ap   = (const float*)d_in[8];
    const float* Bp   = (const float*)d_in[9];
    float* out = (float*)d_out;

    float *p_qkv, *p_ao, *p_t, *p_t2;
    cudaGetSymbolAddress((void**)&p_qkv, g_qkv);
    cudaGetSymbolAddress((void**)&p_ao,  g_ao);
    cudaGetSymbolAddress((void**)&p_t,   g_t);
    cudaGetSymbolAddress((void**)&p_t2,  g_t2);

    cudaFuncSetAttribute(flash_kernel,
                         cudaFuncAttributeMaxDynamicSharedMemorySize,
                         FLASH_SMEM_BYTES);

    // 1. t = x @ Aqkv^T * scale
    lora_t_kernel<<<MROWS, 128>>>(x, Aqkv, p_t);

    // 2. qkv = x @ Wqkv^T + bqkv + t @ Bqkv^T
    gemm_lora_kernel<<<dim3(NQKV / GBN, MROWS / GBM), 256, GEMM_SMEM_BYTES>>>(
        x, Wqkv, bqkv, p_t, Bqkv, p_qkv, CDIM, NQKV);

    // 3. attention
    flash_kernel<<<dim3(NSEQ / FBQ, BATCH * HH), 256, FLASH_SMEM_BYTES>>>(
        p_qkv, mask, p_ao);

    // 4. t2 = ao @ Ap^T * scale
    lora_t_kernel<<<MROWS, 128>>>(p_ao, Ap, p_t2);

    // 5. out = ao @ Wp^T + bp + t2 @ Bp^T
    gemm_lora_kernel<<<dim3(CDIM / GBN, MROWS / GBM), 256, GEMM_SMEM_BYTES>>>(
        p_ao, Wp, bp, p_t2, Bp, out, CDIM, CDIM);
}

// round 8
// speedup vs baseline: 2.4295x; 2.4295x over previous
#include <cuda_runtime.h>
#include <cuda_bf16.h>
#include <cstdint>

// Problem constants (fixed by the dataset)
#define BATCH 2
#define NSEQ  2048
#define CDIM  1024
#define HH    16
#define DD    64
#define RLORA 16
#define MROWS (BATCH * NSEQ)        // 4096
#define NQKV  (3 * CDIM)            // 3072
#define LORA_SCALE 2.0f

// ---------------------------------------------------------------------------
// Scratch (static device globals; no allocation allowed)
// ---------------------------------------------------------------------------
__device__ float g_qkv[MROWS * NQKV];   // 50.3 MB
__device__ float g_ao [MROWS * CDIM];   // 16.8 MB
__device__ float g_t  [MROWS * RLORA];
__device__ float g_t2 [MROWS * RLORA];

// ---------------------------------------------------------------------------
// t = (X @ A^T) * LORA_SCALE
// ---------------------------------------------------------------------------
__global__ __launch_bounds__(128) void lora_t_kernel(
    const float* __restrict__ X, const float* __restrict__ A,
    float* __restrict__ T)
{
    int m   = blockIdx.x;
    int tid = threadIdx.x;
    const float* xr = X + (size_t)m * CDIM;

    float acc[RLORA];
#pragma unroll
    for (int j = 0; j < RLORA; j++) acc[j] = 0.f;

    for (int k = tid; k < CDIM; k += 128) {
        float xv = xr[k];
#pragma unroll
        for (int j = 0; j < RLORA; j++)
            acc[j] += xv * A[j * CDIM + k];
    }

    __shared__ float red[RLORA][4];
    int lane = tid & 31, w = tid >> 5;
#pragma unroll
    for (int j = 0; j < RLORA; j++) {
        float v = acc[j];
#pragma unroll
        for (int off = 16; off; off >>= 1)
            v += __shfl_xor_sync(0xffffffffu, v, off);
        if (lane == 0) red[j][w] = v;
    }
    __syncthreads();
    if (tid < RLORA) {
        float v = red[tid][0] + red[tid][1] + red[tid][2] + red[tid][3];
        T[m * RLORA + tid] = v * LORA_SCALE;
    }
}

// ---------------------------------------------------------------------------
// TF32 mma helpers
// ---------------------------------------------------------------------------
__device__ __forceinline__ uint32_t f2tf32(float f) {
    uint32_t u;
    asm("cvt.rna.tf32.f32 %0, %1;" : "=r"(u) : "f"(f));
    return u;
}

__device__ __forceinline__ void mma_tf32(float d[4],
    uint32_t a0, uint32_t a1, uint32_t a2, uint32_t a3,
    uint32_t b0, uint32_t b1)
{
    asm volatile(
        "mma.sync.aligned.m16n8k8.row.col.f32.tf32.tf32.f32 "
        "{%0,%1,%2,%3}, {%4,%5,%6,%7}, {%8,%9}, {%0,%1,%2,%3};"
        : "+f"(d[0]), "+f"(d[1]), "+f"(d[2]), "+f"(d[3])
        : "r"(a0), "r"(a1), "r"(a2), "r"(a3), "r"(b0), "r"(b1));
}

// ---------------------------------------------------------------------------
// TF32 tensor-core GEMM with fused bias + rank-16 LoRA.
// Tile BM=BN=128, BK=16; 8 warps (4m x 2n); warp tile 32x64.
// Smem [row][k] stride 20 -> fragment LDS conflict-free. Double-buffered.
// ---------------------------------------------------------------------------
#define KSTR 20
#define MTILE (128 * KSTR)   // 2560 words per tile

__global__ __launch_bounds__(256) void gemm_lora_mma(
    const float* __restrict__ A, const float* __restrict__ W,
    const float* __restrict__ bias, const float* __restrict__ T,
    const float* __restrict__ Bl, float* __restrict__ C,
    int K, int Nout)
{
    __shared__ uint32_t sm[4 * MTILE];   // As0 | Ws0 | As1 | Ws1
    uint32_t* AsB[2] = { sm,             sm + 2 * MTILE };
    uint32_t* WsB[2] = { sm + MTILE,     sm + 3 * MTILE };

    int tid  = threadIdx.x;
    int lane = tid & 31, wid = tid >> 5;
    int lr = lane >> 2, lc = lane & 3;
    int warp_m = wid & 3, warp_n = wid >> 2;
    int m0 = blockIdx.y * 128, n0 = blockIdx.x * 128;

    int ldr = tid >> 2;
    int ldq = (tid & 3) * 4;

    float d[2][8][4];
#pragma unroll
    for (int mt = 0; mt < 2; mt++)
#pragma unroll
        for (int nt = 0; nt < 8; nt++)
#pragma unroll
            for (int e = 0; e < 4; e++) d[mt][nt][e] = 0.f;

    const int KT = K / 16;

    {
        float4 a0 = *(const float4*)&A[(size_t)(m0 + ldr)      * K + ldq];
        float4 a1 = *(const float4*)&A[(size_t)(m0 + ldr + 64) * K + ldq];
        float4 w0 = *(const float4*)&W[(size_t)(n0 + ldr)      * K + ldq];
        float4 w1 = *(const float4*)&W[(size_t)(n0 + ldr + 64) * K + ldq];
        uint32_t* As = AsB[0]; uint32_t* Ws = WsB[0];
        As[ldr * KSTR + ldq + 0] = f2tf32(a0.x); As[ldr * KSTR + ldq + 1] = f2tf32(a0.y);
        As[ldr * KSTR + ldq + 2] = f2tf32(a0.z); As[ldr * KSTR + ldq + 3] = f2tf32(a0.w);
        As[(ldr + 64) * KSTR + ldq + 0] = f2tf32(a1.x); As[(ldr + 64) * KSTR + ldq + 1] = f2tf32(a1.y);
        As[(ldr + 64) * KSTR + ldq + 2] = f2tf32(a1.z); As[(ldr + 64) * KSTR + ldq + 3] = f2tf32(a1.w);
        Ws[ldr * KSTR + ldq + 0] = f2tf32(w0.x); Ws[ldr * KSTR + ldq + 1] = f2tf32(w0.y);
        Ws[ldr * KSTR + ldq + 2] = f2tf32(w0.z); Ws[ldr * KSTR + ldq + 3] = f2tf32(w0.w);
        Ws[(ldr + 64) * KSTR + ldq + 0] = f2tf32(w1.x); Ws[(ldr + 64) * KSTR + ldq + 1] = f2tf32(w1.y);
        Ws[(ldr + 64) * KSTR + ldq + 2] = f2tf32(w1.z); Ws[(ldr + 64) * KSTR + ldq + 3] = f2tf32(w1.w);
    }
    __syncthreads();

    for (int kt = 0; kt < KT; kt++) {
        float4 pa0, pa1, pw0, pw1;
        bool hn = (kt + 1 < KT);
        if (hn) {
            int kb = (kt + 1) * 16 + ldq;
            pa0 = *(const float4*)&A[(size_t)(m0 + ldr)      * K + kb];
            pa1 = *(const float4*)&A[(size_t)(m0 + ldr + 64) * K + kb];
            pw0 = *(const float4*)&W[(size_t)(n0 + ldr)      * K + kb];
            pw1 = *(const float4*)&W[(size_t)(n0 + ldr + 64) * K + kb];
        }

        const uint32_t* As = AsB[kt & 1];
        const uint32_t* Ws = WsB[kt & 1];
#pragma unroll
        for (int s = 0; s < 2; s++) {
            int k0 = s * 8;
            uint32_t af[2][4];
#pragma unroll
            for (int mt = 0; mt < 2; mt++) {
                int rb = warp_m * 32 + mt * 16 + lr;
                af[mt][0] = As[rb * KSTR + k0 + lc];
                af[mt][1] = As[(rb + 8) * KSTR + k0 + lc];
                af[mt][2] = As[rb * KSTR + k0 + 4 + lc];
                af[mt][3] = As[(rb + 8) * KSTR + k0 + 4 + lc];
            }
#pragma unroll
            for (int nt = 0; nt < 8; nt++) {
                int nb = warp_n * 64 + nt * 8 + lr;
                uint32_t b0 = Ws[nb * KSTR + k0 + lc];
                uint32_t b1 = Ws[nb * KSTR + k0 + 4 + lc];
                mma_tf32(d[0][nt], af[0][0], af[0][1], af[0][2], af[0][3], b0, b1);
                mma_tf32(d[1][nt], af[1][0], af[1][1], af[1][2], af[1][3], b0, b1);
            }
        }

        if (hn) {
            uint32_t* Asn = AsB[(kt + 1) & 1];
            uint32_t* Wsn = WsB[(kt + 1) & 1];
            Asn[ldr * KSTR + ldq + 0] = f2tf32(pa0.x); Asn[ldr * KSTR + ldq + 1] = f2tf32(pa0.y);
            Asn[ldr * KSTR + ldq + 2] = f2tf32(pa0.z); Asn[ldr * KSTR + ldq + 3] = f2tf32(pa0.w);
            Asn[(ldr + 64) * KSTR + ldq + 0] = f2tf32(pa1.x); Asn[(ldr + 64) * KSTR + ldq + 1] = f2tf32(pa1.y);
            Asn[(ldr + 64) * KSTR + ldq + 2] = f2tf32(pa1.z); Asn[(ldr + 64) * KSTR + ldq + 3] = f2tf32(pa1.w);
            Wsn[ldr * KSTR + ldq + 0] = f2tf32(pw0.x); Wsn[ldr * KSTR + ldq + 1] = f2tf32(pw0.y);
            Wsn[ldr * KSTR + ldq + 2] = f2tf32(pw0.z); Wsn[ldr * KSTR + ldq + 3] = f2tf32(pw0.w);
            Wsn[(ldr + 64) * KSTR + ldq + 0] = f2tf32(pw1.x); Wsn[(ldr + 64) * KSTR + ldq + 1] = f2tf32(pw1.y);
            Wsn[(ldr + 64) * KSTR + ldq + 2] = f2tf32(pw1.z); Wsn[(ldr + 64) * KSTR + ldq + 3] = f2tf32(pw1.w);
            __syncthreads();
        }
    }

    // ---- LoRA rank-16 term: 2 extra mma k-steps ----
    __syncthreads();
    {
        uint32_t* Ts = AsB[0]; uint32_t* Bs = WsB[0];
        float4 t0 = *(const float4*)&T [(size_t)(m0 + ldr)      * RLORA + ldq];
        float4 t1 = *(const float4*)&T [(size_t)(m0 + ldr + 64) * RLORA + ldq];
        float4 u0 = *(const float4*)&Bl[(size_t)(n0 + ldr)      * RLORA + ldq];
        float4 u1 = *(const float4*)&Bl[(size_t)(n0 + ldr + 64) * RLORA + ldq];
        Ts[ldr * KSTR + ldq + 0] = f2tf32(t0.x); Ts[ldr * KSTR + ldq + 1] = f2tf32(t0.y);
        Ts[ldr * KSTR + ldq + 2] = f2tf32(t0.z); Ts[ldr * KSTR + ldq + 3] = f2tf32(t0.w);
        Ts[(ldr + 64) * KSTR + ldq + 0] = f2tf32(t1.x); Ts[(ldr + 64) * KSTR + ldq + 1] = f2tf32(t1.y);
        Ts[(ldr + 64) * KSTR + ldq + 2] = f2tf32(t1.z); Ts[(ldr + 64) * KSTR + ldq + 3] = f2tf32(t1.w);
        Bs[ldr * KSTR + ldq + 0] = f2tf32(u0.x); Bs[ldr * KSTR + ldq + 1] = f2tf32(u0.y);
        Bs[ldr * KSTR + ldq + 2] = f2tf32(u0.z); Bs[ldr * KSTR + ldq + 3] = f2tf32(u0.w);
        Bs[(ldr + 64) * KSTR + ldq + 0] = f2tf32(u1.x); Bs[(ldr + 64) * KSTR + ldq + 1] = f2tf32(u1.y);
        Bs[(ldr + 64) * KSTR + ldq + 2] = f2tf32(u1.z); Bs[(ldr + 64) * KSTR + ldq + 3] = f2tf32(u1.w);
    }
    __syncthreads();
    {
        const uint32_t* Ts = AsB[0];
        const uint32_t* Bs = WsB[0];
#pragma unroll
        for (int s = 0; s < 2; s++) {
            int k0 = s * 8;
            uint32_t af[2][4];
#pragma unroll
            for (int mt = 0; mt < 2; mt++) {
                int rb = warp_m * 32 + mt * 16 + lr;
                af[mt][0] = Ts[rb * KSTR + k0 + lc];
                af[mt][1] = Ts[(rb + 8) * KSTR + k0 + lc];
                af[mt][2] = Ts[rb * KSTR + k0 + 4 + lc];
                af[mt][3] = Ts[(rb + 8) * KSTR + k0 + 4 + lc];
            }
#pragma unroll
            for (int nt = 0; nt < 8; nt++) {
                int nb = warp_n * 64 + nt * 8 + lr;
                uint32_t b0 = Bs[nb * KSTR + k0 + lc];
                uint32_t b1 = Bs[nb * KSTR + k0 + 4 + lc];
                mma_tf32(d[0][nt], af[0][0], af[0][1], af[0][2], af[0][3], b0, b1);
                mma_tf32(d[1][nt], af[1][0], af[1][1], af[1][2], af[1][3], b0, b1);
            }
        }
    }

#pragma unroll
    for (int nt = 0; nt < 8; nt++) {
        int c = n0 + warp_n * 64 + nt * 8 + 2 * lc;
        float2 bb = *(const float2*)&bias[c];
#pragma unroll
        for (int mt = 0; mt < 2; mt++) {
            int r = m0 + warp_m * 32 + mt * 16 + lr;
            float2 v0 = { d[mt][nt][0] + bb.x, d[mt][nt][1] + bb.y };
            float2 v1 = { d[mt][nt][2] + bb.x, d[mt][nt][3] + bb.y };
            *(float2*)&C[(size_t)r * Nout + c]       = v0;
            *(float2*)&C[(size_t)(r + 8) * Nout + c] = v1;
        }
    }
}

// ---------------------------------------------------------------------------
// Flash attention with TF32 mma. One CTA = 128 q-rows of one (b,h); 8 warps,
// warp w owns q-rows [w*16, w*16+16). K-tiles of 64.
// Softmax on D fragments in registers (row = quad; shfl_xor 1,2).
// P stored D-layout as tf32 (STS.64), reloaded A-layout by the SAME warp;
// __syncwarp() orders the cross-lane smem dependency (ITS-safe).
// WAR on Ps across tiles is covered by the loop-top __syncthreads().
// ---------------------------------------------------------------------------
#define QSTR 68
#define KST2 68
#define VSTR 72
#define PSTR 68
#define FLASH_SMEM_BYTES ((128 * QSTR + 64 * KST2 + 64 * VSTR + 128 * PSTR) * 4 + 64 * 4)

__global__ __launch_bounds__(256) void flash_mma_kernel(
    const float* __restrict__ qkv, const int* __restrict__ amask,
    float* __restrict__ ao)
{
    extern __shared__ uint32_t smu[];
    uint32_t* Qs = smu;                       // [128][68] tf32 [q][d]
    uint32_t* Ks = Qs + 128 * QSTR;           // [64][68]  tf32 [kcol][d]
    uint32_t* Vs = Ks + 64 * KST2;            // [64][72]  tf32 [kcol][d]
    uint32_t* Ps = Vs + 64 * VSTR;            // [128][68] tf32 [q][kcol]
    int*      mk = (int*)(Ps + 128 * PSTR);   // [64]

    int bh = blockIdx.y;
    int b  = bh >> 4, h = bh & 15;
    int q0 = blockIdx.x * 128;
    int tid  = threadIdx.x;
    int lane = tid & 31, wid = tid >> 5;
    int lr = lane >> 2, lc = lane & 3;
    int qb = wid * 16;                        // warp's q-row base in tile
    const float scale = 0.125f;
    size_t rowbase = (size_t)b * NSEQ;

    // Load Q tile: 128 rows x 16 f4; convert to tf32, pre-scale; packed STS.128
#pragma unroll
    for (int i = 0; i < 8; i++) {
        int idx = tid + i * 256;
        int row = idx >> 4, f4 = idx & 15;
        float4 v = *(const float4*)&qkv[(rowbase + q0 + row) * NQKV + h * DD + f4 * 4];
        uint4 u = { f2tf32(v.x * scale), f2tf32(v.y * scale),
                    f2tf32(v.z * scale), f2tf32(v.w * scale) };
        *(uint4*)&Qs[row * QSTR + f4 * 4] = u;
    }

    float o[8][4];
    float m_i[2] = { -1e30f, -1e30f };
    float l_i[2] = { 0.f, 0.f };
#pragma unroll
    for (int nt = 0; nt < 8; nt++)
#pragma unroll
        for (int e = 0; e < 4; e++) o[nt][e] = 0.f;

    for (int kt = 0; kt < NSEQ / 64; kt++) {
        int k0g = kt * 64;
        __syncthreads();   // all warps done reading Ks/Vs/Ps from previous tile

        // Load K and V tiles (64 rows x 16 f4 each), tf32, packed STS.128
#pragma unroll
        for (int i = 0; i < 4; i++) {
            int idx = tid + i * 256;
            int row = idx >> 4, f4 = idx & 15;
            size_t g = (rowbase + k0g + row) * NQKV + h * DD + f4 * 4;
            float4 kv = *(const float4*)&qkv[g + CDIM];
            uint4 uk = { f2tf32(kv.x), f2tf32(kv.y), f2tf32(kv.z), f2tf32(kv.w) };
            *(uint4*)&Ks[row * KST2 + f4 * 4] = uk;
            float4 vv = *(const float4*)&qkv[g + 2 * CDIM];
            uint4 uv = { f2tf32(vv.x), f2tf32(vv.y), f2tf32(vv.z), f2tf32(vv.w) };
            *(uint4*)&Vs[row * VSTR + f4 * 4] = uv;
        }
        if (tid < 64) mk[tid] = amask[b * NSEQ + k0g + tid];
        __syncthreads();

        // ---- S = Q K^T (8 n8-frags over kcol, 8 k-steps over d) ----
        float s[8][4];
#pragma unroll
        for (int nt = 0; nt < 8; nt++)
#pragma unroll
            for (int e = 0; e < 4; e++) s[nt][e] = 0.f;

#pragma unroll
        for (int ks = 0; ks < 8; ks++) {
            int k0 = ks * 8;
            uint32_t a0 = Qs[(qb + lr) * QSTR + k0 + lc];
            uint32_t a1 = Qs[(qb + lr + 8) * QSTR + k0 + lc];
            uint32_t a2 = Qs[(qb + lr) * QSTR + k0 + 4 + lc];
            uint32_t a3 = Qs[(qb + lr + 8) * QSTR + k0 + 4 + lc];
#pragma unroll
            for (int nt = 0; nt < 8; nt++) {
                uint32_t b0 = Ks[(nt * 8 + lr) * KST2 + k0 + lc];
                uint32_t b1 = Ks[(nt * 8 + lr) * KST2 + k0 + 4 + lc];
                mma_tf32(s[nt], a0, a1, a2, a3, b0, b1);
            }
        }

        // ---- masked online softmax on fragments ----
        float rmax0 = -1e30f, rmax1 = -1e30f;
#pragma unroll
        for (int nt = 0; nt < 8; nt++) {
            bool f0 = mk[nt * 8 + 2 * lc] != 0;
            bool f1 = mk[nt * 8 + 2 * lc + 1] != 0;
            s[nt][0] = f0 ? s[nt][0] : -1e30f;
            s[nt][1] = f1 ? s[nt][1] : -1e30f;
            s[nt][2] = f0 ? s[nt][2] : -1e30f;
            s[nt][3] = f1 ? s[nt][3] : -1e30f;
            rmax0 = fmaxf(rmax0, fmaxf(s[nt][0], s[nt][1]));
            rmax1 = fmaxf(rmax1, fmaxf(s[nt][2], s[nt][3]));
        }
        rmax0 = fmaxf(rmax0, __shfl_xor_sync(0xffffffffu, rmax0, 1));
        rmax0 = fmaxf(rmax0, __shfl_xor_sync(0xffffffffu, rmax0, 2));
        rmax1 = fmaxf(rmax1, __shfl_xor_sync(0xffffffffu, rmax1, 1));
        rmax1 = fmaxf(rmax1, __shfl_xor_sync(0xffffffffu, rmax1, 2));

        float mnew0 = fmaxf(m_i[0], rmax0);
        float mnew1 = fmaxf(m_i[1], rmax1);
        float corr0 = __expf(m_i[0] - mnew0);
        float corr1 = __expf(m_i[1] - mnew1);
        m_i[0] = mnew0; m_i[1] = mnew1;

        float sum0 = 0.f, sum1 = 0.f;
#pragma unroll
        for (int nt = 0; nt < 8; nt++) {
            float f0 = mk[nt * 8 + 2 * lc]     ? 1.f : 0.f;
            float f1 = mk[nt * 8 + 2 * lc + 1] ? 1.f : 0.f;
            float p0 = __expf(s[nt][0] - mnew0) * f0;
            float p1 = __expf(s[nt][1] - mnew0) * f1;
            float p2 = __expf(s[nt][2] - mnew1) * f0;
            float p3 = __expf(s[nt][3] - mnew1) * f1;
            sum0 += p0 + p1; sum1 += p2 + p3;
            uint2 lo = { f2tf32(p0), f2tf32(p1) };
            uint2 hi = { f2tf32(p2), f2tf32(p3) };
            *(uint2*)&Ps[(qb + lr) * PSTR + nt * 8 + 2 * lc]     = lo;
            *(uint2*)&Ps[(qb + lr + 8) * PSTR + nt * 8 + 2 * lc] = hi;
            // rescale O accumulators
            o[nt][0] *= corr0; o[nt][1] *= corr0;
            o[nt][2] *= corr1; o[nt][3] *= corr1;
        }
        sum0 += __shfl_xor_sync(0xffffffffu, sum0, 1);
        sum0 += __shfl_xor_sync(0xffffffffu, sum0, 2);
        sum1 += __shfl_xor_sync(0xffffffffu, sum1, 1);
        sum1 += __shfl_xor_sync(0xffffffffu, sum1, 2);
        l_i[0] = l_i[0] * corr0 + sum0;
        l_i[1] = l_i[1] * corr1 + sum1;

        // Order cross-lane Ps stores before cross-lane Ps loads (ITS-safe).
        __syncwarp();

        // ---- O += P V ----
#pragma unroll
        for (int ks = 0; ks < 8; ks++) {
            int k0 = ks * 8;
            uint32_t a0 = Ps[(qb + lr) * PSTR + k0 + lc];
            uint32_t a1 = Ps[(qb + lr + 8) * PSTR + k0 + lc];
            uint32_t a2 = Ps[(qb + lr) * PSTR + k0 + 4 + lc];
            uint32_t a3 = Ps[(qb + lr + 8) * PSTR + k0 + 4 + lc];
#pragma unroll
            for (int nt = 0; nt < 8; nt++) {
                uint32_t b0 = Vs[(k0 + lc) * VSTR + nt * 8 + lr];
                uint32_t b1 = Vs[(k0 + 4 + lc) * VSTR + nt * 8 + lr];
                mma_tf32(o[nt], a0, a1, a2, a3, b0, b1);
            }
        }
    }

    // ---- normalize + store ----
    float inv0 = 1.0f / l_i[0];
    float inv1 = 1.0f / l_i[1];
    size_t r0 = rowbase + q0 + qb + lr;
    size_t r1 = r0 + 8;
#pragma unroll
    for (int nt = 0; nt < 8; nt++) {
        int c = h * DD + nt * 8 + 2 * lc;
        float2 v0 = { o[nt][0] * inv0, o[nt][1] * inv0 };
        float2 v1 = { o[nt][2] * inv1, o[nt][3] * inv1 };
        *(float2*)&ao[r0 * CDIM + c] = v0;
        *(float2*)&ao[r1 * CDIM + c] = v1;
    }
}

// ---------------------------------------------------------------------------
// Launch
// ---------------------------------------------------------------------------
extern "C" void kernel_launch(void* const* d_in, const int* in_sizes, int n_in,
                              void* d_out, int out_size)
{
    const float* x    = (const float*)d_in[0];
    const int*   mask = (const int*)  d_in[1];
    const float* Wqkv = (const float*)d_in[2];
    const float* bqkv = (const float*)d_in[3];
    const float* Aqkv = (const float*)d_in[4];
    const float* Bqkv = (const float*)d_in[5];
    const float* Wp   = (const float*)d_in[6];
    const float* bp   = (const float*)d_in[7];
    const float* Ap   = (const float*)d_in[8];
    const float* Bp   = (const float*)d_in[9];
    float* out = (float*)d_out;

    float *p_qkv, *p_ao, *p_t, *p_t2;
    cudaGetSymbolAddress((void**)&p_qkv, g_qkv);
    cudaGetSymbolAddress((void**)&p_ao,  g_ao);
    cudaGetSymbolAddress((void**)&p_t,   g_t);
    cudaGetSymbolAddress((void**)&p_t2,  g_t2);

    cudaFuncSetAttribute(flash_mma_kernel,
                         cudaFuncAttributeMaxDynamicSharedMemorySize,
                         FLASH_SMEM_BYTES);

    // 1. t = x @ Aqkv^T * scale
    lora_t_kernel<<<MROWS, 128>>>(x, Aqkv, p_t);

    // 2. qkv = x @ Wqkv^T + bqkv + t @ Bqkv^T   (tf32 tensor cores)
    gemm_lora_mma<<<dim3(NQKV / 128, MROWS / 128), 256>>>(
        x, Wqkv, bqkv, p_t, Bqkv, p_qkv, CDIM, NQKV);

    // 3. attention (tf32 tensor cores)
    flash_mma_kernel<<<dim3(NSEQ / 128, BATCH * HH), 256, FLASH_SMEM_BYTES>>>(
        p_qkv, mask, p_ao);

    // 4. t2 = ao @ Ap^T * scale
    lora_t_kernel<<<MROWS, 128>>>(p_ao, Ap, p_t2);

    // 5. out = ao @ Wp^T + bp + t2 @ Bp^T   (tf32 tensor cores)
    gemm_lora_mma<<<dim3(CDIM / 128, MROWS / 128), 256>>>(
        p_ao, Wp, bp, p_t2, Bp, out, CDIM, CDIM);
}

// round 16
// speedup vs baseline: 3.2996x; 1.3582x over previous
#include <cuda_runtime.h>
#include <cuda_bf16.h>
#include <cstdint>

// Problem constants (fixed by the dataset)
#define BATCH 2
#define NSEQ  2048
#define CDIM  1024
#define HH    16
#define DD    64
#define RLORA 16
#define MROWS (BATCH * NSEQ)        // 4096
#define NQKV  (3 * CDIM)            // 3072
#define LORA_SCALE 2.0f

// ---------------------------------------------------------------------------
// Scratch (static device globals; no allocation allowed).
// All intermediate tensors hold tf32 BIT PATTERNS in uint32 (converted once).
// ---------------------------------------------------------------------------
__device__ uint32_t g_qkv[MROWS * NQKV];   // 50.3 MB tf32 qkv
__device__ uint32_t g_ao [MROWS * CDIM];   // 16.8 MB tf32 attention out
__device__ uint32_t g_wq [NQKV * CDIM];    // 12.6 MB tf32 folded Wqkv
__device__ uint32_t g_wp [CDIM * CDIM];    //  4.2 MB tf32 folded Wp
__device__ uint32_t g_xt [MROWS * CDIM];   // 16.8 MB tf32 x

// ---------------------------------------------------------------------------
// TF32 helpers
// ---------------------------------------------------------------------------
__device__ __forceinline__ uint32_t f2tf32(float f) {
    uint32_t u;
    asm("cvt.rna.tf32.f32 %0, %1;" : "=r"(u) : "f"(f));
    return u;
}

__device__ __forceinline__ void mma_tf32(float d[4],
    uint32_t a0, uint32_t a1, uint32_t a2, uint32_t a3,
    uint32_t b0, uint32_t b1)
{
    asm volatile(
        "mma.sync.aligned.m16n8k8.row.col.f32.tf32.tf32.f32 "
        "{%0,%1,%2,%3}, {%4,%5,%6,%7}, {%8,%9}, {%0,%1,%2,%3};"
        : "+f"(d[0]), "+f"(d[1]), "+f"(d[2]), "+f"(d[3])
        : "r"(a0), "r"(a1), "r"(a2), "r"(a3), "r"(b0), "r"(b1));
}

__device__ __forceinline__ void ldsm_x4(uint32_t& r0, uint32_t& r1,
                                        uint32_t& r2, uint32_t& r3,
                                        uint32_t saddr)
{
    asm volatile(
        "ldmatrix.sync.aligned.m8n8.x4.shared.b16 {%0,%1,%2,%3}, [%4];"
        : "=r"(r0), "=r"(r1), "=r"(r2), "=r"(r3) : "r"(saddr));
}

// ---------------------------------------------------------------------------
// Prep: fold LoRA into weights AND convert everything to tf32 bits.
//  blocks [0, NQKV)                : Wq' row = Wq + 2*Bq@Aq   -> g_wq (tf32)
//  blocks [NQKV, NQKV+CDIM)        : Wp' row                  -> g_wp (tf32)
//  blocks [NQKV+CDIM, +MROWS)      : x row                    -> g_xt (tf32)
// ---------------------------------------------------------------------------
__global__ __launch_bounds__(256) void prep_kernel(
    const float* __restrict__ x,
    const float* __restrict__ Wq, const float* __restrict__ Bq,
    const float* __restrict__ Aq,
    const float* __restrict__ Wp, const float* __restrict__ Bp,
    const float* __restrict__ Ap,
    uint32_t* __restrict__ WqO, uint32_t* __restrict__ WpO,
    uint32_t* __restrict__ xO)
{
    int n = blockIdx.x;
    int k = threadIdx.x * 4;

    if (n >= NQKV + CDIM) {
        int row = n - (NQKV + CDIM);
        float4 v = *(const float4*)&x[(size_t)row * CDIM + k];
        uint4 u = { f2tf32(v.x), f2tf32(v.y), f2tf32(v.z), f2tf32(v.w) };
        *(uint4*)&xO[(size_t)row * CDIM + k] = u;
        return;
    }

    const float *W, *Bm, *Am;
    uint32_t* O;
    int row;
    if (n < NQKV) { W = Wq; Bm = Bq; Am = Aq; O = WqO; row = n; }
    else          { W = Wp; Bm = Bp; Am = Ap; O = WpO; row = n - NQKV; }

    float br[RLORA];
#pragma unroll
    for (int l = 0; l < RLORA; l++) br[l] = Bm[row * RLORA + l];

    float4 sum = { 0.f, 0.f, 0.f, 0.f };
#pragma unroll
    for (int l = 0; l < RLORA; l++) {
        float4 a = *(const float4*)&Am[l * CDIM + k];
        sum.x += br[l] * a.x; sum.y += br[l] * a.y;
        sum.z += br[l] * a.z; sum.w += br[l] * a.w;
    }
    float4 w = *(const float4*)&W[(size_t)row * CDIM + k];
    uint4 u = { f2tf32(w.x + LORA_SCALE * sum.x),
                f2tf32(w.y + LORA_SCALE * sum.y),
                f2tf32(w.z + LORA_SCALE * sum.z),
                f2tf32(w.w + LORA_SCALE * sum.w) };
    *(uint4*)&O[(size_t)row * CDIM + k] = u;
}

// ---------------------------------------------------------------------------
// Pure TF32 tensor-core GEMM + bias. Inputs are tf32 bits (no cvt in loop).
// OUT_TF32: C stored as tf32 bits (for qkv); else fp32 (final out).
// Tile BM=BN=128, BK=16; 8 warps (4m x 2n); warp tile 32x64.
// Fragments via ldmatrix.x4. Double-buffered, register prefetch, STS.128.
// __launch_bounds__(256, 2): cap regs at 124 so 2 CTAs/SM co-reside.
// ---------------------------------------------------------------------------
#define KSTR 20
#define MTILE (128 * KSTR)   // 2560 words per tile

template<bool OUT_TF32>
__global__ __launch_bounds__(256, 2) void gemm_mma(
    const uint32_t* __restrict__ A, const uint32_t* __restrict__ W,
    const float* __restrict__ bias, void* __restrict__ Cv,
    int K, int Nout)
{
    __shared__ uint32_t sm[4 * MTILE];   // As0 | Ws0 | As1 | Ws1
    uint32_t* AsB[2] = { sm,             sm + 2 * MTILE };
    uint32_t* WsB[2] = { sm + MTILE,     sm + 3 * MTILE };

    int tid  = threadIdx.x;
    int lane = tid & 31, wid = tid >> 5;
    int lr = lane >> 2, lc = lane & 3;
    int warp_m = wid & 3, warp_n = wid >> 2;
    int m0 = blockIdx.y * 128, n0 = blockIdx.x * 128;

    int ldr = tid >> 2;
    int ldq = (tid & 3) * 4;

    // ldmatrix lane address components
    int ajrow = lane & 15;
    int ajk   = (lane >> 4) << 2;
    int bjrow = (lane & 7) + ((lane >> 4) << 3);
    int bjk   = (lane & 8) ? 4 : 0;
    uint32_t aoff[2], boff[4];
#pragma unroll
    for (int mt = 0; mt < 2; mt++)
        aoff[mt] = ((warp_m * 32 + mt * 16 + ajrow) * KSTR + ajk) * 4;
#pragma unroll
    for (int p = 0; p < 4; p++)
        boff[p] = ((warp_n * 64 + p * 16 + bjrow) * KSTR + bjk) * 4;

    uint32_t asbase[2], wsbase[2];
#pragma unroll
    for (int bf = 0; bf < 2; bf++) {
        asbase[bf] = (uint32_t)__cvta_generic_to_shared(AsB[bf]);
        wsbase[bf] = (uint32_t)__cvta_generic_to_shared(WsB[bf]);
    }

    float d[2][8][4];
#pragma unroll
    for (int mt = 0; mt < 2; mt++)
#pragma unroll
        for (int nt = 0; nt < 8; nt++)
#pragma unroll
            for (int e = 0; e < 4; e++) d[mt][nt][e] = 0.f;

    const int KT = K / 16;

    {
        uint4 ua0 = *(const uint4*)&A[(size_t)(m0 + ldr)      * K + ldq];
        uint4 ua1 = *(const uint4*)&A[(size_t)(m0 + ldr + 64) * K + ldq];
        uint4 uw0 = *(const uint4*)&W[(size_t)(n0 + ldr)      * K + ldq];
        uint4 uw1 = *(const uint4*)&W[(size_t)(n0 + ldr + 64) * K + ldq];
        *(uint4*)&AsB[0][ldr * KSTR + ldq]        = ua0;
        *(uint4*)&AsB[0][(ldr + 64) * KSTR + ldq] = ua1;
        *(uint4*)&WsB[0][ldr * KSTR + ldq]        = uw0;
        *(uint4*)&WsB[0][(ldr + 64) * KSTR + ldq] = uw1;
    }
    __syncthreads();

    for (int kt = 0; kt < KT; kt++) {
        uint4 pa0, pa1, pw0, pw1;
        bool hn = (kt + 1 < KT);
        if (hn) {
            int kb = (kt + 1) * 16 + ldq;
            pa0 = *(const uint4*)&A[(size_t)(m0 + ldr)      * K + kb];
            pa1 = *(const uint4*)&A[(size_t)(m0 + ldr + 64) * K + kb];
            pw0 = *(const uint4*)&W[(size_t)(n0 + ldr)      * K + kb];
            pw1 = *(const uint4*)&W[(size_t)(n0 + ldr + 64) * K + kb];
        }

        uint32_t ab = asbase[kt & 1], wb = wsbase[kt & 1];
#pragma unroll
        for (int s = 0; s < 2; s++) {
            uint32_t kofs = s * 32;
            uint32_t af[2][4];
#pragma unroll
            for (int mt = 0; mt < 2; mt++)
                ldsm_x4(af[mt][0], af[mt][1], af[mt][2], af[mt][3],
                        ab + aoff[mt] + kofs);
#pragma unroll
            for (int p = 0; p < 4; p++) {
                uint32_t b00, b01, b10, b11;
                ldsm_x4(b00, b01, b10, b11, wb + boff[p] + kofs);
                mma_tf32(d[0][2 * p],     af[0][0], af[0][1], af[0][2], af[0][3], b00, b01);
                mma_tf32(d[1][2 * p],     af[1][0], af[1][1], af[1][2], af[1][3], b00, b01);
                mma_tf32(d[0][2 * p + 1], af[0][0], af[0][1], af[0][2], af[0][3], b10, b11);
                mma_tf32(d[1][2 * p + 1], af[1][0], af[1][1], af[1][2], af[1][3], b10, b11);
            }
        }

        if (hn) {
            uint32_t* Asn = AsB[(kt + 1) & 1];
            uint32_t* Wsn = WsB[(kt + 1) & 1];
            *(uint4*)&Asn[ldr * KSTR + ldq]        = pa0;
            *(uint4*)&Asn[(ldr + 64) * KSTR + ldq] = pa1;
            *(uint4*)&Wsn[ldr * KSTR + ldq]        = pw0;
            *(uint4*)&Wsn[(ldr + 64) * KSTR + ldq] = pw1;
            __syncthreads();
        }
    }

    // ---- bias + store ----
#pragma unroll
    for (int nt = 0; nt < 8; nt++) {
        int c = n0 + warp_n * 64 + nt * 8 + 2 * lc;
        float2 bb = *(const float2*)&bias[c];
#pragma unroll
        for (int mt = 0; mt < 2; mt++) {
            int r = m0 + warp_m * 32 + mt * 16 + lr;
            float v00 = d[mt][nt][0] + bb.x, v01 = d[mt][nt][1] + bb.y;
            float v10 = d[mt][nt][2] + bb.x, v11 = d[mt][nt][3] + bb.y;
            if (OUT_TF32) {
                uint32_t* C = (uint32_t*)Cv;
                uint2 u0 = { f2tf32(v00), f2tf32(v01) };
                uint2 u1 = { f2tf32(v10), f2tf32(v11) };
                *(uint2*)&C[(size_t)r * Nout + c]       = u0;
                *(uint2*)&C[(size_t)(r + 8) * Nout + c] = u1;
            } else {
                float* C = (float*)Cv;
                float2 u0 = { v00, v01 };
                float2 u1 = { v10, v11 };
                *(float2*)&C[(size_t)r * Nout + c]       = u0;
                *(float2*)&C[(size_t)(r + 8) * Nout + c] = u1;
            }
        }
    }
}

// ---------------------------------------------------------------------------
// Flash attention with TF32 mma + ldmatrix. qkv already tf32 bits (no cvt).
// One CTA = 128 q-rows of one (b,h); 8 warps; K-tiles of 64.
// Q unscaled in smem; S scaled by 0.125 after QK mma (exact, power of two).
// Output ao written as tf32 bits for gemm2.
// __launch_bounds__(256, 2): 2 CTAs/SM (2 x 105.7KB smem fits in 228KB
// carveout; regs capped 124, live set ~95); carveout hint pinned host-side.
// ---------------------------------------------------------------------------
#define QSTR 68
#define KST2 68
#define VSTR 72
#define PSTR 68
#define FLASH_SMEM_BYTES ((128 * QSTR + 64 * KST2 + 64 * VSTR + 128 * PSTR) * 4 + 64 * 4)

__global__ __launch_bounds__(256, 2) void flash_mma_kernel(
    const uint32_t* __restrict__ qkv, const int* __restrict__ amask,
    uint32_t* __restrict__ ao)
{
    extern __shared__ uint32_t smu[];
    uint32_t* Qs = smu;                       // [128][68] tf32 [q][d]
    uint32_t* Ks = Qs + 128 * QSTR;           // [64][68]  tf32 [kcol][d]
    uint32_t* Vs = Ks + 64 * KST2;            // [64][72]  tf32 [kcol][d]
    uint32_t* Ps = Vs + 64 * VSTR;            // [128][68] tf32 [q][kcol]
    int*      mk = (int*)(Ps + 128 * PSTR);   // [64]

    int bh = blockIdx.y;
    int b  = bh >> 4, h = bh & 15;
    int q0 = blockIdx.x * 128;
    int tid  = threadIdx.x;
    int lane = tid & 31, wid = tid >> 5;
    int lr = lane >> 2, lc = lane & 3;
    int qb = wid * 16;
    const float scale = 0.125f;
    size_t rowbase = (size_t)b * NSEQ;

    // ldmatrix lane address components
    int ajrow = lane & 15;
    int ajk   = (lane >> 4) << 2;
    int bjrow = (lane & 7) + ((lane >> 4) << 3);
    int bjk   = (lane & 8) ? 4 : 0;

    uint32_t qsb = (uint32_t)__cvta_generic_to_shared(Qs);
    uint32_t ksb = (uint32_t)__cvta_generic_to_shared(Ks);
    uint32_t psb = (uint32_t)__cvta_generic_to_shared(Ps);

    uint32_t qaddr = qsb + ((qb + ajrow) * QSTR + ajk) * 4;
    uint32_t paddr = psb + ((qb + ajrow) * PSTR + ajk) * 4;
    uint32_t kaddr[4];
#pragma unroll
    for (int p = 0; p < 4; p++)
        kaddr[p] = ksb + ((p * 16 + bjrow) * KST2 + bjk) * 4;

    // Q tile: raw tf32 bit copy (no cvt, no scale)
#pragma unroll
    for (int i = 0; i < 8; i++) {
        int idx = tid + i * 256;
        int row = idx >> 4, f4 = idx & 15;
        uint4 u = *(const uint4*)&qkv[(rowbase + q0 + row) * NQKV + h * DD + f4 * 4];
        *(uint4*)&Qs[row * QSTR + f4 * 4] = u;
    }

    float o[8][4];
    float m_i[2] = { -1e30f, -1e30f };
    float l_i[2] = { 0.f, 0.f };
#pragma unroll
    for (int nt = 0; nt < 8; nt++)
#pragma unroll
        for (int e = 0; e < 4; e++) o[nt][e] = 0.f;

    for (int kt = 0; kt < NSEQ / 64; kt++) {
        int k0g = kt * 64;
        __syncthreads();   // all warps done reading Ks/Vs/Ps from previous tile

#pragma unroll
        for (int i = 0; i < 4; i++) {
            int idx = tid + i * 256;
            int row = idx >> 4, f4 = idx & 15;
            size_t g = (rowbase + k0g + row) * NQKV + h * DD + f4 * 4;
            *(uint4*)&Ks[row * KST2 + f4 * 4] = *(const uint4*)&qkv[g + CDIM];
            *(uint4*)&Vs[row * VSTR + f4 * 4] = *(const uint4*)&qkv[g + 2 * CDIM];
        }
        if (tid < 64) mk[tid] = amask[b * NSEQ + k0g + tid];
        __syncthreads();

        // ---- S = Q K^T via ldmatrix fragments ----
        float s[8][4];
#pragma unroll
        for (int nt = 0; nt < 8; nt++)
#pragma unroll
            for (int e = 0; e < 4; e++) s[nt][e] = 0.f;

#pragma unroll
        for (int ks = 0; ks < 8; ks++) {
            uint32_t kofs = ks * 32;
            uint32_t a0, a1, a2, a3;
            ldsm_x4(a0, a1, a2, a3, qaddr + kofs);
#pragma unroll
            for (int p = 0; p < 4; p++) {
                uint32_t b00, b01, b10, b11;
                ldsm_x4(b00, b01, b10, b11, kaddr[p] + kofs);
                mma_tf32(s[2 * p],     a0, a1, a2, a3, b00, b01);
                mma_tf32(s[2 * p + 1], a0, a1, a2, a3, b10, b11);
            }
        }

        // ---- scale + masked online softmax on fragments ----
        float rmax0 = -1e30f, rmax1 = -1e30f;
#pragma unroll
        for (int nt = 0; nt < 8; nt++) {
            bool f0 = mk[nt * 8 + 2 * lc] != 0;
            bool f1 = mk[nt * 8 + 2 * lc + 1] != 0;
            s[nt][0] = f0 ? s[nt][0] * scale : -1e30f;
            s[nt][1] = f1 ? s[nt][1] * scale : -1e30f;
            s[nt][2] = f0 ? s[nt][2] * scale : -1e30f;
            s[nt][3] = f1 ? s[nt][3] * scale : -1e30f;
            rmax0 = fmaxf(rmax0, fmaxf(s[nt][0], s[nt][1]));
            rmax1 = fmaxf(rmax1, fmaxf(s[nt][2], s[nt][3]));
        }
        rmax0 = fmaxf(rmax0, __shfl_xor_sync(0xffffffffu, rmax0, 1));
        rmax0 = fmaxf(rmax0, __shfl_xor_sync(0xffffffffu, rmax0, 2));
        rmax1 = fmaxf(rmax1, __shfl_xor_sync(0xffffffffu, rmax1, 1));
        rmax1 = fmaxf(rmax1, __shfl_xor_sync(0xffffffffu, rmax1, 2));

        float mnew0 = fmaxf(m_i[0], rmax0);
        float mnew1 = fmaxf(m_i[1], rmax1);
        float corr0 = __expf(m_i[0] - mnew0);
        float corr1 = __expf(m_i[1] - mnew1);
        m_i[0] = mnew0; m_i[1] = mnew1;

        float sum0 = 0.f, sum1 = 0.f;
#pragma unroll
        for (int nt = 0; nt < 8; nt++) {
            float f0 = mk[nt * 8 + 2 * lc]     ? 1.f : 0.f;
            float f1 = mk[nt * 8 + 2 * lc + 1] ? 1.f : 0.f;
            float p0 = __expf(s[nt][0] - mnew0) * f0;
            float p1 = __expf(s[nt][1] - mnew0) * f1;
            float p2 = __expf(s[nt][2] - mnew1) * f0;
            float p3 = __expf(s[nt][3] - mnew1) * f1;
            sum0 += p0 + p1; sum1 += p2 + p3;
            uint2 lo = { f2tf32(p0), f2tf32(p1) };
            uint2 hi = { f2tf32(p2), f2tf32(p3) };
            *(uint2*)&Ps[(qb + lr) * PSTR + nt * 8 + 2 * lc]     = lo;
            *(uint2*)&Ps[(qb + lr + 8) * PSTR + nt * 8 + 2 * lc] = hi;
            o[nt][0] *= corr0; o[nt][1] *= corr0;
            o[nt][2] *= corr1; o[nt][3] *= corr1;
        }
        sum0 += __shfl_xor_sync(0xffffffffu, sum0, 1);
        sum0 += __shfl_xor_sync(0xffffffffu, sum0, 2);
        sum1 += __shfl_xor_sync(0xffffffffu, sum1, 1);
        sum1 += __shfl_xor_sync(0xffffffffu, sum1, 2);
        l_i[0] = l_i[0] * corr0 + sum0;
        l_i[1] = l_i[1] * corr1 + sum1;

        // Order cross-lane Ps stores before cross-lane Ps reads (ldmatrix).
        __syncwarp();

        // ---- O += P V (P via ldmatrix, V via scalar LDS) ----
#pragma unroll
        for (int ks = 0; ks < 8; ks++) {
            int k0 = ks * 8;
            uint32_t a0, a1, a2, a3;
            ldsm_x4(a0, a1, a2, a3, paddr + ks * 32);
#pragma unroll
            for (int nt = 0; nt < 8; nt++) {
                uint32_t b0 = Vs[(k0 + lc) * VSTR + nt * 8 + lr];
                uint32_t b1 = Vs[(k0 + 4 + lc) * VSTR + nt * 8 + lr];
                mma_tf32(o[nt], a0, a1, a2, a3, b0, b1);
            }
        }
    }

    // ---- normalize + store as tf32 bits ----
    float inv0 = 1.0f / l_i[0];
    float inv1 = 1.0f / l_i[1];
    size_t r0 = rowbase + q0 + qb + lr;
    size_t r1 = r0 + 8;
#pragma unroll
    for (int nt = 0; nt < 8; nt++) {
        int c = h * DD + nt * 8 + 2 * lc;
        uint2 v0 = { f2tf32(o[nt][0] * inv0), f2tf32(o[nt][1] * inv0) };
        uint2 v1 = { f2tf32(o[nt][2] * inv1), f2tf32(o[nt][3] * inv1) };
        *(uint2*)&ao[r0 * CDIM + c] = v0;
        *(uint2*)&ao[r1 * CDIM + c] = v1;
    }
}

// ---------------------------------------------------------------------------
// Launch: [prep, gemm_qkv, flash, gemm_proj]  (4 launches)
// ---------------------------------------------------------------------------
extern "C" void kernel_launch(void* const* d_in, const int* in_sizes, int n_in,
                              void* d_out, int out_size)
{
    const float* x    = (const float*)d_in[0];
    const int*   mask = (const int*)  d_in[1];
    const float* Wqkv = (const float*)d_in[2];
    const float* bqkv = (const float*)d_in[3];
    const float* Aqkv = (const float*)d_in[4];
    const float* Bqkv = (const float*)d_in[5];
    const float* Wp   = (const float*)d_in[6];
    const float* bp   = (const float*)d_in[7];
    const float* Ap   = (const float*)d_in[8];
    const float* Bp   = (const float*)d_in[9];
    float* out = (float*)d_out;

    uint32_t *p_qkv, *p_ao, *p_wq, *p_wp, *p_xt;
    cudaGetSymbolAddress((void**)&p_qkv, g_qkv);
    cudaGetSymbolAddress((void**)&p_ao,  g_ao);
    cudaGetSymbolAddress((void**)&p_wq,  g_wq);
    cudaGetSymbolAddress((void**)&p_wp,  g_wp);
    cudaGetSymbolAddress((void**)&p_xt,  g_xt);

    cudaFuncSetAttribute(flash_mma_kernel,
                         cudaFuncAttributeMaxDynamicSharedMemorySize,
                         FLASH_SMEM_BYTES);
    // Pin the unified-cache split at max shared so 2 flash CTAs/SM co-reside.
    cudaFuncSetAttribute(flash_mma_kernel,
                         cudaFuncAttributePreferredSharedMemoryCarveout, 100);

    // 1. fold LoRA into weights + convert weights/x to tf32 bits
    prep_kernel<<<NQKV + CDIM + MROWS, 256>>>(
        x, Wqkv, Bqkv, Aqkv, Wp, Bp, Ap, p_wq, p_wp, p_xt);

    // 2. qkv = x @ Wq'^T + bqkv   (tf32 in, tf32 bits out)
    gemm_mma<true><<<dim3(NQKV / 128, MROWS / 128), 256>>>(
        p_xt, p_wq, bqkv, p_qkv, CDIM, NQKV);

    // 3. attention (tf32 in, tf32 bits out)
    flash_mma_kernel<<<dim3(NSEQ / 128, BATCH * HH), 256, FLASH_SMEM_BYTES>>>(
        p_qkv, mask, p_ao);

    // 4. out = ao @ Wp'^T + bp   (tf32 in, fp32 out)
    gemm_mma<false><<<dim3(CDIM / 128, MROWS / 128), 256>>>(
        p_ao, p_wp, bp, out, CDIM, CDIM);
}

// round 17
// speedup vs baseline: 3.3672x; 1.0205x over previous
#include <cuda_runtime.h>
#include <cuda_bf16.h>
#include <cstdint>

// Problem constants (fixed by the dataset)
#define BATCH 2
#define NSEQ  2048
#define CDIM  1024
#define HH    16
#define DD    64
#define RLORA 16
#define MROWS (BATCH * NSEQ)        // 4096
#define NQKV  (3 * CDIM)            // 3072
#define LORA_SCALE 2.0f

// ---------------------------------------------------------------------------
// Scratch (static device globals; no allocation allowed).
// All intermediate tensors hold tf32 BIT PATTERNS in uint32 (converted once).
// ---------------------------------------------------------------------------
__device__ uint32_t g_qkv[MROWS * NQKV];   // 50.3 MB tf32 qkv
__device__ uint32_t g_ao [MROWS * CDIM];   // 16.8 MB tf32 attention out
__device__ uint32_t g_wq [NQKV * CDIM];    // 12.6 MB tf32 folded Wqkv
__device__ uint32_t g_wp [CDIM * CDIM];    //  4.2 MB tf32 folded Wp
__device__ uint32_t g_xt [MROWS * CDIM];   // 16.8 MB tf32 x

// ---------------------------------------------------------------------------
// TF32 helpers
// ---------------------------------------------------------------------------
__device__ __forceinline__ uint32_t f2tf32(float f) {
    uint32_t u;
    asm("cvt.rna.tf32.f32 %0, %1;" : "=r"(u) : "f"(f));
    return u;
}

__device__ __forceinline__ void mma_tf32(float d[4],
    uint32_t a0, uint32_t a1, uint32_t a2, uint32_t a3,
    uint32_t b0, uint32_t b1)
{
    asm volatile(
        "mma.sync.aligned.m16n8k8.row.col.f32.tf32.tf32.f32 "
        "{%0,%1,%2,%3}, {%4,%5,%6,%7}, {%8,%9}, {%0,%1,%2,%3};"
        : "+f"(d[0]), "+f"(d[1]), "+f"(d[2]), "+f"(d[3])
        : "r"(a0), "r"(a1), "r"(a2), "r"(a3), "r"(b0), "r"(b1));
}

__device__ __forceinline__ void ldsm_x4(uint32_t& r0, uint32_t& r1,
                                        uint32_t& r2, uint32_t& r3,
                                        uint32_t saddr)
{
    asm volatile(
        "ldmatrix.sync.aligned.m8n8.x4.shared.b16 {%0,%1,%2,%3}, [%4];"
        : "=r"(r0), "=r"(r1), "=r"(r2), "=r"(r3) : "r"(saddr));
}

// ---------------------------------------------------------------------------
// Prep: fold LoRA into weights AND convert everything to tf32 bits.
//  blocks [0, NQKV)                : Wq' row = Wq + 2*Bq@Aq   -> g_wq (tf32)
//  blocks [NQKV, NQKV+CDIM)        : Wp' row                  -> g_wp (tf32)
//  blocks [NQKV+CDIM, +MROWS)      : x row                    -> g_xt (tf32)
// ---------------------------------------------------------------------------
__global__ __launch_bounds__(256) void prep_kernel(
    const float* __restrict__ x,
    const float* __restrict__ Wq, const float* __restrict__ Bq,
    const float* __restrict__ Aq,
    const float* __restrict__ Wp, const float* __restrict__ Bp,
    const float* __restrict__ Ap,
    uint32_t* __restrict__ WqO, uint32_t* __restrict__ WpO,
    uint32_t* __restrict__ xO)
{
    int n = blockIdx.x;
    int k = threadIdx.x * 4;

    if (n >= NQKV + CDIM) {
        int row = n - (NQKV + CDIM);
        float4 v = *(const float4*)&x[(size_t)row * CDIM + k];
        uint4 u = { f2tf32(v.x), f2tf32(v.y), f2tf32(v.z), f2tf32(v.w) };
        *(uint4*)&xO[(size_t)row * CDIM + k] = u;
        return;
    }

    const float *W, *Bm, *Am;
    uint32_t* O;
    int row;
    if (n < NQKV) { W = Wq; Bm = Bq; Am = Aq; O = WqO; row = n; }
    else          { W = Wp; Bm = Bp; Am = Ap; O = WpO; row = n - NQKV; }

    float br[RLORA];
#pragma unroll
    for (int l = 0; l < RLORA; l++) br[l] = Bm[row * RLORA + l];

    float4 sum = { 0.f, 0.f, 0.f, 0.f };
#pragma unroll
    for (int l = 0; l < RLORA; l++) {
        float4 a = *(const float4*)&Am[l * CDIM + k];
        sum.x += br[l] * a.x; sum.y += br[l] * a.y;
        sum.z += br[l] * a.z; sum.w += br[l] * a.w;
    }
    float4 w = *(const float4*)&W[(size_t)row * CDIM + k];
    uint4 u = { f2tf32(w.x + LORA_SCALE * sum.x),
                f2tf32(w.y + LORA_SCALE * sum.y),
                f2tf32(w.z + LORA_SCALE * sum.z),
                f2tf32(w.w + LORA_SCALE * sum.w) };
    *(uint4*)&O[(size_t)row * CDIM + k] = u;
}

// ---------------------------------------------------------------------------
// Pure TF32 tensor-core GEMM + bias. Inputs are tf32 bits (no cvt in loop).
// OUT_TF32: C stored as tf32 bits (for qkv); else fp32 (final out).
// Tile BM=BN=128, BK=16; 4 warps (2m x 2n); warp tile 64x64.
// Read amplification = warps_m + warps_n = 4 (was 6 with 8 warps 4x2):
// per s, 4 A-ldsm + 4 B-ldsm feed 32 mma -> 128 B/mma smem traffic (-33%),
// attacking the measured l1tex=72.7% bottleneck.
// Fragments via ldmatrix.x4. Double-buffered, register prefetch, STS.128.
// __launch_bounds__(128, 2): 2 CTAs/SM; reg cap 256 (live set ~200).
// ---------------------------------------------------------------------------
#define KSTR 20
#define MTILE (128 * KSTR)   // 2560 words per tile

template<bool OUT_TF32>
__global__ __launch_bounds__(128, 2) void gemm_mma(
    const uint32_t* __restrict__ A, const uint32_t* __restrict__ W,
    const float* __restrict__ bias, void* __restrict__ Cv,
    int K, int Nout)
{
    __shared__ uint32_t sm[4 * MTILE];   // As0 | Ws0 | As1 | Ws1
    uint32_t* AsB[2] = { sm,             sm + 2 * MTILE };
    uint32_t* WsB[2] = { sm + MTILE,     sm + 3 * MTILE };

    int tid  = threadIdx.x;
    int lane = tid & 31, wid = tid >> 5;          // 4 warps
    int lr = lane >> 2, lc = lane & 3;
    int warp_m = wid & 1, warp_n = wid >> 1;      // 2m x 2n
    int m0 = blockIdx.y * 128, n0 = blockIdx.x * 128;

    int ldr = tid >> 2;          // 0..31
    int ldq = (tid & 3) * 4;

    // ldmatrix lane address components
    int ajrow = lane & 15;
    int ajk   = (lane >> 4) << 2;
    int bjrow = (lane & 7) + ((lane >> 4) << 3);
    int bjk   = (lane & 8) ? 4 : 0;
    uint32_t aoff[4], boff[4];
#pragma unroll
    for (int mt = 0; mt < 4; mt++)
        aoff[mt] = ((warp_m * 64 + mt * 16 + ajrow) * KSTR + ajk) * 4;
#pragma unroll
    for (int p = 0; p < 4; p++)
        boff[p] = ((warp_n * 64 + p * 16 + bjrow) * KSTR + bjk) * 4;

    uint32_t asbase[2], wsbase[2];
#pragma unroll
    for (int bf = 0; bf < 2; bf++) {
        asbase[bf] = (uint32_t)__cvta_generic_to_shared(AsB[bf]);
        wsbase[bf] = (uint32_t)__cvta_generic_to_shared(WsB[bf]);
    }

    float d[4][8][4];
#pragma unroll
    for (int mt = 0; mt < 4; mt++)
#pragma unroll
        for (int nt = 0; nt < 8; nt++)
#pragma unroll
            for (int e = 0; e < 4; e++) d[mt][nt][e] = 0.f;

    const int KT = K / 16;

    // ---- stage tile 0: 4 A rows + 4 W rows per thread (rows ldr+32i) ----
    {
#pragma unroll
        for (int i = 0; i < 4; i++) {
            int row = ldr + 32 * i;
            uint4 ua = *(const uint4*)&A[(size_t)(m0 + row) * K + ldq];
            uint4 uw = *(const uint4*)&W[(size_t)(n0 + row) * K + ldq];
            *(uint4*)&AsB[0][row * KSTR + ldq] = ua;
            *(uint4*)&WsB[0][row * KSTR + ldq] = uw;
        }
    }
    __syncthreads();

    for (int kt = 0; kt < KT; kt++) {
        uint4 pa[4], pw[4];
        bool hn = (kt + 1 < KT);
        if (hn) {
            int kb = (kt + 1) * 16 + ldq;
#pragma unroll
            for (int i = 0; i < 4; i++) {
                int row = ldr + 32 * i;
                pa[i] = *(const uint4*)&A[(size_t)(m0 + row) * K + kb];
                pw[i] = *(const uint4*)&W[(size_t)(n0 + row) * K + kb];
            }
        }

        uint32_t ab = asbase[kt & 1], wb = wsbase[kt & 1];
#pragma unroll
        for (int s = 0; s < 2; s++) {
            uint32_t kofs = s * 32;
            uint32_t af[4][4];
#pragma unroll
            for (int mt = 0; mt < 4; mt++)
                ldsm_x4(af[mt][0], af[mt][1], af[mt][2], af[mt][3],
                        ab + aoff[mt] + kofs);
#pragma unroll
            for (int p = 0; p < 4; p++) {
                uint32_t b00, b01, b10, b11;
                ldsm_x4(b00, b01, b10, b11, wb + boff[p] + kofs);
#pragma unroll
                for (int mt = 0; mt < 4; mt++) {
                    mma_tf32(d[mt][2 * p],     af[mt][0], af[mt][1], af[mt][2], af[mt][3], b00, b01);
                    mma_tf32(d[mt][2 * p + 1], af[mt][0], af[mt][1], af[mt][2], af[mt][3], b10, b11);
                }
            }
        }

        if (hn) {
            uint32_t* Asn = AsB[(kt + 1) & 1];
            uint32_t* Wsn = WsB[(kt + 1) & 1];
#pragma unroll
            for (int i = 0; i < 4; i++) {
                int row = ldr + 32 * i;
                *(uint4*)&Asn[row * KSTR + ldq] = pa[i];
                *(uint4*)&Wsn[row * KSTR + ldq] = pw[i];
            }
            __syncthreads();
        }
    }

    // ---- bias + store ----
#pragma unroll
    for (int nt = 0; nt < 8; nt++) {
        int c = n0 + warp_n * 64 + nt * 8 + 2 * lc;
        float2 bb = *(const float2*)&bias[c];
#pragma unroll
        for (int mt = 0; mt < 4; mt++) {
            int r = m0 + warp_m * 64 + mt * 16 + lr;
            float v00 = d[mt][nt][0] + bb.x, v01 = d[mt][nt][1] + bb.y;
            float v10 = d[mt][nt][2] + bb.x, v11 = d[mt][nt][3] + bb.y;
            if (OUT_TF32) {
                uint32_t* C = (uint32_t*)Cv;
                uint2 u0 = { f2tf32(v00), f2tf32(v01) };
                uint2 u1 = { f2tf32(v10), f2tf32(v11) };
                *(uint2*)&C[(size_t)r * Nout + c]       = u0;
                *(uint2*)&C[(size_t)(r + 8) * Nout + c] = u1;
            } else {
                float* C = (float*)Cv;
                float2 u0 = { v00, v01 };
                float2 u1 = { v10, v11 };
                *(float2*)&C[(size_t)r * Nout + c]       = u0;
                *(float2*)&C[(size_t)(r + 8) * Nout + c] = u1;
            }
        }
    }
}

// ---------------------------------------------------------------------------
// Flash attention with TF32 mma + ldmatrix (UNCHANGED from 603.7us kernel).
// ---------------------------------------------------------------------------
#define QSTR 68
#define KST2 68
#define VSTR 72
#define PSTR 68
#define FLASH_SMEM_BYTES ((128 * QSTR + 64 * KST2 + 64 * VSTR + 128 * PSTR) * 4 + 64 * 4)

__global__ __launch_bounds__(256, 2) void flash_mma_kernel(
    const uint32_t* __restrict__ qkv, const int* __restrict__ amask,
    uint32_t* __restrict__ ao)
{
    extern __shared__ uint32_t smu[];
    uint32_t* Qs = smu;                       // [128][68] tf32 [q][d]
    uint32_t* Ks = Qs + 128 * QSTR;           // [64][68]  tf32 [kcol][d]
    uint32_t* Vs = Ks + 64 * KST2;            // [64][72]  tf32 [kcol][d]
    uint32_t* Ps = Vs + 64 * VSTR;            // [128][68] tf32 [q][kcol]
    int*      mk = (int*)(Ps + 128 * PSTR);   // [64]

    int bh = blockIdx.y;
    int b  = bh >> 4, h = bh & 15;
    int q0 = blockIdx.x * 128;
    int tid  = threadIdx.x;
    int lane = tid & 31, wid = tid >> 5;
    int lr = lane >> 2, lc = lane & 3;
    int qb = wid * 16;
    const float scale = 0.125f;
    size_t rowbase = (size_t)b * NSEQ;

    int ajrow = lane & 15;
    int ajk   = (lane >> 4) << 2;
    int bjrow = (lane & 7) + ((lane >> 4) << 3);
    int bjk   = (lane & 8) ? 4 : 0;

    uint32_t qsb = (uint32_t)__cvta_generic_to_shared(Qs);
    uint32_t ksb = (uint32_t)__cvta_generic_to_shared(Ks);
    uint32_t psb = (uint32_t)__cvta_generic_to_shared(Ps);

    uint32_t qaddr = qsb + ((qb + ajrow) * QSTR + ajk) * 4;
    uint32_t paddr = psb + ((qb + ajrow) * PSTR + ajk) * 4;
    uint32_t kaddr[4];
#pragma unroll
    for (int p = 0; p < 4; p++)
        kaddr[p] = ksb + ((p * 16 + bjrow) * KST2 + bjk) * 4;

#pragma unroll
    for (int i = 0; i < 8; i++) {
        int idx = tid + i * 256;
        int row = idx >> 4, f4 = idx & 15;
        uint4 u = *(const uint4*)&qkv[(rowbase + q0 + row) * NQKV + h * DD + f4 * 4];
        *(uint4*)&Qs[row * QSTR + f4 * 4] = u;
    }

    float o[8][4];
    float m_i[2] = { -1e30f, -1e30f };
    float l_i[2] = { 0.f, 0.f };
#pragma unroll
    for (int nt = 0; nt < 8; nt++)
#pragma unroll
        for (int e = 0; e < 4; e++) o[nt][e] = 0.f;

    for (int kt = 0; kt < NSEQ / 64; kt++) {
        int k0g = kt * 64;
        __syncthreads();

#pragma unroll
        for (int i = 0; i < 4; i++) {
            int idx = tid + i * 256;
            int row = idx >> 4, f4 = idx & 15;
            size_t g = (rowbase + k0g + row) * NQKV + h * DD + f4 * 4;
            *(uint4*)&Ks[row * KST2 + f4 * 4] = *(const uint4*)&qkv[g + CDIM];
            *(uint4*)&Vs[row * VSTR + f4 * 4] = *(const uint4*)&qkv[g + 2 * CDIM];
        }
        if (tid < 64) mk[tid] = amask[b * NSEQ + k0g + tid];
        __syncthreads();

        float s[8][4];
#pragma unroll
        for (int nt = 0; nt < 8; nt++)
#pragma unroll
            for (int e = 0; e < 4; e++) s[nt][e] = 0.f;

#pragma unroll
        for (int ks = 0; ks < 8; ks++) {
            uint32_t kofs = ks * 32;
            uint32_t a0, a1, a2, a3;
            ldsm_x4(a0, a1, a2, a3, qaddr + kofs);
#pragma unroll
            for (int p = 0; p < 4; p++) {
                uint32_t b00, b01, b10, b11;
                ldsm_x4(b00, b01, b10, b11, kaddr[p] + kofs);
                mma_tf32(s[2 * p],     a0, a1, a2, a3, b00, b01);
                mma_tf32(s[2 * p + 1], a0, a1, a2, a3, b10, b11);
            }
        }

        float rmax0 = -1e30f, rmax1 = -1e30f;
#pragma unroll
        for (int nt = 0; nt < 8; nt++) {
            bool f0 = mk[nt * 8 + 2 * lc] != 0;
            bool f1 = mk[nt * 8 + 2 * lc + 1] != 0;
            s[nt][0] = f0 ? s[nt][0] * scale : -1e30f;
            s[nt][1] = f1 ? s[nt][1] * scale : -1e30f;
            s[nt][2] = f0 ? s[nt][2] * scale : -1e30f;
            s[nt][3] = f1 ? s[nt][3] * scale : -1e30f;
            rmax0 = fmaxf(rmax0, fmaxf(s[nt][0], s[nt][1]));
            rmax1 = fmaxf(rmax1, fmaxf(s[nt][2], s[nt][3]));
        }
        rmax0 = fmaxf(rmax0, __shfl_xor_sync(0xffffffffu, rmax0, 1));
        rmax0 = fmaxf(rmax0, __shfl_xor_sync(0xffffffffu, rmax0, 2));
        rmax1 = fmaxf(rmax1, __shfl_xor_sync(0xffffffffu, rmax1, 1));
        rmax1 = fmaxf(rmax1, __shfl_xor_sync(0xffffffffu, rmax1, 2));

        float mnew0 = fmaxf(m_i[0], rmax0);
        float mnew1 = fmaxf(m_i[1], rmax1);
        float corr0 = __expf(m_i[0] - mnew0);
        float corr1 = __expf(m_i[1] - mnew1);
        m_i[0] = mnew0; m_i[1] = mnew1;

        float sum0 = 0.f, sum1 = 0.f;
#pragma unroll
        for (int nt = 0; nt < 8; nt++) {
            float f0 = mk[nt * 8 + 2 * lc]     ? 1.f : 0.f;
            float f1 = mk[nt * 8 + 2 * lc + 1] ? 1.f : 0.f;
            float p0 = __expf(s[nt][0] - mnew0) * f0;
            float p1 = __expf(s[nt][1] - mnew0) * f1;
            float p2 = __expf(s[nt][2] - mnew1) * f0;
            float p3 = __expf(s[nt][3] - mnew1) * f1;
            sum0 += p0 + p1; sum1 += p2 + p3;
            uint2 lo = { f2tf32(p0), f2tf32(p1) };
            uint2 hi = { f2tf32(p2), f2tf32(p3) };
            *(uint2*)&Ps[(qb + lr) * PSTR + nt * 8 + 2 * lc]     = lo;
            *(uint2*)&Ps[(qb + lr + 8) * PSTR + nt * 8 + 2 * lc] = hi;
            o[nt][0] *= corr0; o[nt][1] *= corr0;
            o[nt][2] *= corr1; o[nt][3] *= corr1;
        }
        sum0 += __shfl_xor_sync(0xffffffffu, sum0, 1);
        sum0 += __shfl_xor_sync(0xffffffffu, sum0, 2);
        sum1 += __shfl_xor_sync(0xffffffffu, sum1, 1);
        sum1 += __shfl_xor_sync(0xffffffffu, sum1, 2);
        l_i[0] = l_i[0] * corr0 + sum0;
        l_i[1] = l_i[1] * corr1 + sum1;

        __syncwarp();

#pragma unroll
        for (int ks = 0; ks < 8; ks++) {
            int k0 = ks * 8;
            uint32_t a0, a1, a2, a3;
            ldsm_x4(a0, a1, a2, a3, paddr + ks * 32);
#pragma unroll
            for (int nt = 0; nt < 8; nt++) {
                uint32_t b0 = Vs[(k0 + lc) * VSTR + nt * 8 + lr];
                uint32_t b1 = Vs[(k0 + 4 + lc) * VSTR + nt * 8 + lr];
                mma_tf32(o[nt], a0, a1, a2, a3, b0, b1);
            }
        }
    }

    float inv0 = 1.0f / l_i[0];
    float inv1 = 1.0f / l_i[1];
    size_t r0 = rowbase + q0 + qb + lr;
    size_t r1 = r0 + 8;
#pragma unroll
    for (int nt = 0; nt < 8; nt++) {
        int c = h * DD + nt * 8 + 2 * lc;
        uint2 v0 = { f2tf32(o[nt][0] * inv0), f2tf32(o[nt][1] * inv0) };
        uint2 v1 = { f2tf32(o[nt][2] * inv1), f2tf32(o[nt][3] * inv1) };
        *(uint2*)&ao[r0 * CDIM + c] = v0;
        *(uint2*)&ao[r1 * CDIM + c] = v1;
    }
}

// ---------------------------------------------------------------------------
// Launch: [prep, gemm_qkv, flash, gemm_proj]  (4 launches)
// ---------------------------------------------------------------------------
extern "C" void kernel_launch(void* const* d_in, const int* in_sizes, int n_in,
                              void* d_out, int out_size)
{
    const float* x    = (const float*)d_in[0];
    const int*   mask = (const int*)  d_in[1];
    const float* Wqkv = (const float*)d_in[2];
    const float* bqkv = (const float*)d_in[3];
    const float* Aqkv = (const float*)d_in[4];
    const float* Bqkv = (const float*)d_in[5];
    const float* Wp   = (const float*)d_in[6];
    const float* bp   = (const float*)d_in[7];
    const float* Ap   = (const float*)d_in[8];
    const float* Bp   = (const float*)d_in[9];
    float* out = (float*)d_out;

    uint32_t *p_qkv, *p_ao, *p_wq, *p_wp, *p_xt;
    cudaGetSymbolAddress((void**)&p_qkv, g_qkv);
    cudaGetSymbolAddress((void**)&p_ao,  g_ao);
    cudaGetSymbolAddress((void**)&p_wq,  g_wq);
    cudaGetSymbolAddress((void**)&p_wp,  g_wp);
    cudaGetSymbolAddress((void**)&p_xt,  g_xt);

    cudaFuncSetAttribute(flash_mma_kernel,
                         cudaFuncAttributeMaxDynamicSharedMemorySize,
                         FLASH_SMEM_BYTES);
    // Pin the unified-cache split at max shared so 2 flash CTAs/SM co-reside.
    cudaFuncSetAttribute(flash_mma_kernel,
                         cudaFuncAttributePreferredSharedMemoryCarveout, 100);

    // 1. fold LoRA into weights + convert weights/x to tf32 bits
    prep_kernel<<<NQKV + CDIM + MROWS, 256>>>(
        x, Wqkv, Bqkv, Aqkv, Wp, Bp, Ap, p_wq, p_wp, p_xt);

    // 2. qkv = x @ Wq'^T + bqkv   (tf32 in, tf32 bits out)
    gemm_mma<true><<<dim3(NQKV / 128, MROWS / 128), 128>>>(
        p_xt, p_wq, bqkv, p_qkv, CDIM, NQKV);

    // 3. attention (tf32 in, tf32 bits out)
    flash_mma_kernel<<<dim3(NSEQ / 128, BATCH * HH), 256, FLASH_SMEM_BYTES>>>(
        p_qkv, mask, p_ao);

    // 4. out = ao @ Wp'^T + bp   (tf32 in, fp32 out)
    gemm_mma<false><<<dim3(CDIM / 128, MROWS / 128), 128>>>(
        p_ao, p_wp, bp, out, CDIM, CDIM);
}